// round 10
// baseline (speedup 1.0000x reference)
#include <cuda_runtime.h>
#include <cuda_fp16.h>
#include <cstdint>

// Problem constants
#define NG        2048
#define NPG       512
#define CPG       128
#define CPG2      32

// Padded k-strides (halves). stride/2 banks ≡ 4 (mod 8) -> conflict-free frag loads
#define KP2 56    // P2 A + W2l  (K used = 48)
#define KF2 72    // F2 A + W2g  (K used = 64)
#define KP3 136   // P3 A + W3l  (K used = 128)

__device__ __forceinline__ float celu1(float x) {
    return fmaxf(x, 0.f) + (__expf(fminf(x, 0.f)) - 1.f);
}

// ---------------------------------------------------------------------------
// Global scratch
// ---------------------------------------------------------------------------
__device__ float g_agg3m[NG * 128];
__device__ __align__(16) __half g_w2lH[64 * KP2];     //  7KB  W2l^T [n=64][k=56]
__device__ __align__(16) __half g_w2gH[128 * KF2];    // 18KB  W2g^T [n=128][k=72]
__device__ __align__(16) __half g_w3lH[128 * KP3];    // 34KB  W3l^T [n=128][k=136]

// ---------------------------------------------------------------------------
// HMMA m16n8k16 helpers (fp16 in, fp32 accum) — plain sm_103-legal PTX
// ---------------------------------------------------------------------------
__device__ __forceinline__ void mma16816(float* c, const uint32_t* a, uint32_t b0, uint32_t b1) {
    asm volatile("mma.sync.aligned.m16n8k16.row.col.f32.f16.f16.f32 "
        "{%0,%1,%2,%3}, {%4,%5,%6,%7}, {%8,%9}, {%0,%1,%2,%3};"
        : "+f"(c[0]), "+f"(c[1]), "+f"(c[2]), "+f"(c[3])
        : "r"(a[0]), "r"(a[1]), "r"(a[2]), "r"(a[3]), "r"(b0), "r"(b1));
}
// A fragment: rows g,g+8 of a 16-row tile, k-cols k0+tig*2 (+1), k0+8+tig*2 (+1)
__device__ __forceinline__ void ldA(uint32_t* a, const __half* A, int stride, int g, int tig, int k0) {
    a[0] = *(const uint32_t*)(A + g * stride + k0 + tig * 2);
    a[1] = *(const uint32_t*)(A + (g + 8) * stride + k0 + tig * 2);
    a[2] = *(const uint32_t*)(A + g * stride + k0 + 8 + tig * 2);
    a[3] = *(const uint32_t*)(A + (g + 8) * stride + k0 + 8 + tig * 2);
}

// ---------------------------------------------------------------------------
// Prep kernel: fp16 transposed padded weight images (once per launch)
// ---------------------------------------------------------------------------
__global__ void prep_kernel(const float* __restrict__ W2l,
                            const float* __restrict__ W2g,
                            const float* __restrict__ W3l)
{
    int i = blockIdx.x * 256 + threadIdx.x;
    const int N0 = 64 * KP2, N1 = 128 * KF2, N2 = 128 * KP3;
    if (i < N0) {
        int n = i / KP2, k = i % KP2;
        g_w2lH[i] = __float2half(k < 35 ? W2l[k * 64 + n] : 0.f);
    } else if (i < N0 + N1) {
        int j = i - N0; int n = j / KF2, k = j % KF2;
        g_w2gH[j] = __float2half(k < 64 ? W2g[k * 128 + n] : 0.f);
    } else if (i < N0 + N1 + N2) {
        int j = i - N0 - N1; int n = j / KP3, k = j % KP3;
        g_w3lH[j] = __float2half(k < 128 ? W3l[k * 128 + n] : 0.f);
    }
}

// ---------------------------------------------------------------------------
// Shared-memory float-index layout (dynamic, 27696 floats = 110784 B -> occ 2)
// ---------------------------------------------------------------------------
#define F_POS1   0       // 384
#define F_POS2   384     // 96
#define F_W1L    480     // 64
#define F_B1L    544     // 16
#define F_W1G    560     // 512
#define F_B1G    1072    // 32
#define F_B2L    1104    // 64
#define F_B2G    1168    // 128
#define F_B3L    1296    // 128
#define F_W3P    1424    // 384 (W3l rows 128..130)
#define I_S1     1808    // 128 int
#define I_SLOT   1936
#define I_SSEG   2064
#define I_OFF1   2192
#define I_OFF1F  2320
#define I_OFF2F  2448    // 32
#define I_CNT1   2480    // 128
#define I_CNT2   2608    // 32
#define F_STAGE  2640    // 4256: stX/stP/stS/plist -> agg2T[64][36] -> P3tmp[32][133]
#define F_AGG1T  6896    // 2112 ([16][132])
#define F_AH     9008    // 3584: aP2[128][56]h  -> aF2[32][72]h @+0, aP3[32][136]h @+1152
#define F_W2L    12592   // 1792 (w2lS halves)
#define F_W2G    14384   // 4608
#define F_W3L    18992   // 8704
#define F_TOT    27696
#define SMEM_BYTES (F_TOT * 4)

__global__ __launch_bounds__(256) void glimpse_kernel(
    const float* __restrict__ rgb,  const float* __restrict__ pos,
    const float* __restrict__ pos1, const float* __restrict__ pos2,
    const int* __restrict__ idx0, const int* __restrict__ idx1,
    const float* __restrict__ W1l, const float* __restrict__ b1l,
    const float* __restrict__ W1g, const float* __restrict__ b1g,
    const float* __restrict__ b2l, const float* __restrict__ b2g,
    const float* __restrict__ W3l, const float* __restrict__ b3l)
{
    extern __shared__ __align__(16) float sm[];
    int* smi = (int*)sm;

    float* pos1L = sm + F_POS1;
    float* pos2L = sm + F_POS2;
    float* W1lS  = sm + F_W1L;
    float* b1lS  = sm + F_B1L;
    float* W1gS  = sm + F_W1G;
    float* b1gS  = sm + F_B1G;
    float* b2lS  = sm + F_B2L;
    float* b2gS  = sm + F_B2G;
    float* b3lS  = sm + F_B3L;
    float* W3P   = sm + F_W3P;
    int*   s1    = smi + I_S1;
    int*   slot  = smi + I_SLOT;
    int*   sseg  = smi + I_SSEG;
    int*   off1  = smi + I_OFF1;
    int*   off1f = smi + I_OFF1F;
    int*   off2f = smi + I_OFF2F;
    int*   cnt1i = smi + I_CNT1;
    int*   cnt2i = smi + I_CNT2;
    float* stX   = sm + F_STAGE;
    float* stPx  = sm + F_STAGE + 512;
    float* stPy  = sm + F_STAGE + 1024;
    float* stPz  = sm + F_STAGE + 1536;
    int*   stS   = smi + F_STAGE + 2048;
    int*   plist = smi + F_STAGE + 2560;
    float* agg2T = sm + F_STAGE;              // [64][36], after staging dies
    float* P3tmp = sm + F_STAGE;              // [32][133], after agg2T dies
    float* agg1T = sm + F_AGG1T;              // [16][132]
    __half* aP2  = (__half*)(sm + F_AH);      // [128][KP2]
    __half* aF2  = (__half*)(sm + F_AH);      // [32][KF2]   (aP2 dead)
    __half* aP3  = (__half*)(sm + F_AH + 1152); // [32][KP3]
    __half* w2lS = (__half*)(sm + F_W2L);
    __half* w2gS = (__half*)(sm + F_W2G);
    __half* w3lS = (__half*)(sm + F_W3L);

    const int t = threadIdx.x;
    const int wid = t >> 5;
    const int lane = t & 31;
    const int g = blockIdx.x;
    const int fg = lane >> 2;     // fragment row group 0..7
    const int tig = lane & 3;     // thread-in-group

    // ---- block 0: loads + zeros + weight smem copies ----
    for (int i = t; i < 384; i += 256) pos1L[i] = pos1[g * 384 + i];
    for (int i = t; i < 96;  i += 256) pos2L[i] = pos2[g * 96 + i];
    if (t < 64) { W1lS[t] = W1l[t]; b2lS[t] = b2l[t]; }
    if (t < 16) b1lS[t] = b1l[t];
    for (int i = t; i < 512; i += 256) W1gS[i] = W1g[i];
    if (t < 32) b1gS[t] = b1g[t];
    for (int i = t; i < 128; i += 256) { b2gS[i] = b2g[i]; b3lS[i] = b3l[i]; cnt1i[i] = 0; }
    for (int i = t; i < 384; i += 256) W3P[i] = W3l[128 * 128 + i];
    if (t < 32) cnt2i[t] = 0;
    for (int i = t; i < 2112; i += 256) agg1T[i] = 0.f;
    {
        uint4* d0 = (uint4*)w2lS; const uint4* s0 = (const uint4*)g_w2lH;
        uint4* d1 = (uint4*)w2gS; const uint4* s1_ = (const uint4*)g_w2gH;
        uint4* d2 = (uint4*)w3lS; const uint4* s2 = (const uint4*)g_w3lH;
        for (int i = t; i < 64 * KP2 / 8;  i += 256) d0[i] = s0[i];
        for (int i = t; i < 128 * KF2 / 8; i += 256) d1[i] = s1_[i];
        for (int i = t; i < 128 * KP3 / 8; i += 256) d2[i] = s2[i];
    }
    __syncthreads();

    // ---- block 1: stage points + counts ----
    for (int p = t; p < 512; p += 256) {
        stX[p] = rgb[g * 512 + p];
        int s = (idx0[g * 512 + p] - g * CPG) & (CPG - 1);
        stS[p] = s;
        atomicAdd(&cnt1i[s], 1);
    }
    for (int i = t; i < 1536; i += 256) {
        float v = pos[g * 1536 + i];
        int p = i / 3, c = i - p * 3;
        if (c == 0) stPx[p] = v; else if (c == 1) stPy[p] = v; else stPz[p] = v;
    }
    if (t < 128) {
        int s = (idx1[g * 128 + t] - g * CPG2) & (CPG2 - 1);
        s1[t] = s;
        atomicAdd(&cnt2i[s], 1);
    }
    __syncthreads();

    // ---- block 2: prefix sums ----
    if (t < 32) {
        int carry = 0;
        for (int c = 0; c < 4; c++) {
            int v = cnt1i[c * 32 + t];
            int x = v;
            #pragma unroll
            for (int d = 1; d < 32; d <<= 1) {
                int y = __shfl_up_sync(0xffffffffu, x, d);
                if (t >= d) x += y;
            }
            int excl = x - v + carry;
            off1[c * 32 + t] = excl;
            off1f[c * 32 + t] = excl;
            carry += __shfl_sync(0xffffffffu, x, 31);
        }
    } else if (t < 64) {
        int ln = t - 32;
        int v = cnt2i[ln];
        int x = v;
        #pragma unroll
        for (int d = 1; d < 32; d <<= 1) {
            int y = __shfl_up_sync(0xffffffffu, x, d);
            if (ln >= d) x += y;
        }
        off2f[ln] = x - v;
    }
    __syncthreads();

    // ---- block 3: scatter sorted point list + row slots ----
    for (int p = t; p < 512; p += 256) {
        int s = stS[p];
        int pp = atomicAdd(&off1f[s], 1);
        plist[pp] = p;
    }
    if (t < 128) {
        int s = s1[t];
        int q = atomicAdd(&off2f[s], 1);
        slot[t] = q;
        sseg[q] = s;
    }
    __syncthreads();

    // ---- block 4: phase-1 accumulate + rel/pad rows into aP2 ----
    {
        int s = t >> 1, jb = (t & 1) * 8;
        int cnt = cnt1i[s], base = off1[s];
        float acc[8];
        #pragma unroll
        for (int j = 0; j < 8; j++) acc[j] = 0.f;
        const float c1x = pos1L[s * 3 + 0], c1y = pos1L[s * 3 + 1], c1z = pos1L[s * 3 + 2];
        for (int e = 0; e < cnt; e++) {
            int p = plist[base + e];
            float x0 = stX[p];
            float rx = stPx[p] - c1x, ry = stPy[p] - c1y, rz = stPz[p] - c1z;
            #pragma unroll
            for (int j = 0; j < 8; j++) {
                float h = b1lS[jb + j] + x0 * W1lS[jb + j] + rx * W1lS[16 + jb + j]
                        + ry * W1lS[32 + jb + j] + rz * W1lS[48 + jb + j];
                acc[j] += celu1(h);
            }
        }
        float inv = 1.f / (float)max(cnt, 1);
        #pragma unroll
        for (int j = 0; j < 8; j++) agg1T[(jb + j) * 132 + s] = acc[j] * inv;
    }
    if (t < 128) {
        int r = t, q = slot[r], s = s1[r];
        __half* row = aP2 + q * KP2;
        row[32] = __float2half(pos1L[r * 3 + 0] - pos2L[s * 3 + 0]);
        row[33] = __float2half(pos1L[r * 3 + 1] - pos2L[s * 3 + 1]);
        row[34] = __float2half(pos1L[r * 3 + 2] - pos2L[s * 3 + 2]);
        #pragma unroll
        for (int k = 35; k < 48; k++) row[k] = __float2half(0.f);
    }
    __syncthreads();

    // ---- f1 GEMM (scalar, tiny) -> aP2 cols 0..31 ; also zero agg2T ----
    {
        int ob = t & 7, rb = t >> 3;
        int r0 = rb * 4, o0 = ob * 4;
        float acc[4][4];
        #pragma unroll
        for (int ri = 0; ri < 4; ri++)
            #pragma unroll
            for (int oi = 0; oi < 4; oi++) acc[ri][oi] = b1gS[o0 + oi];
        #pragma unroll
        for (int j = 0; j < 16; j++) {
            float4 x = *(const float4*)&agg1T[j * 132 + r0];
            float4 w = *(const float4*)&W1gS[j * 32 + o0];
            float xa[4] = {x.x, x.y, x.z, x.w};
            float wa[4] = {w.x, w.y, w.z, w.w};
            #pragma unroll
            for (int ri = 0; ri < 4; ri++)
                #pragma unroll
                for (int oi = 0; oi < 4; oi++) acc[ri][oi] += xa[ri] * wa[oi];
        }
        #pragma unroll
        for (int ri = 0; ri < 4; ri++) {
            int q = slot[r0 + ri];
            *(__half2*)&aP2[q * KP2 + o0]     = __floats2half2_rn(celu1(acc[ri][0]), celu1(acc[ri][1]));
            *(__half2*)&aP2[q * KP2 + o0 + 2] = __floats2half2_rn(celu1(acc[ri][2]), celu1(acc[ri][3]));
        }
    }
    for (int i = t; i < 64 * 36; i += 256) agg2T[i] = 0.f;   // staging is dead now
    __syncthreads();

    // ---- P2 HMMA: C[128x64] = aP2[128x48] @ W2l^T, warp w -> rows w*16.. ----
    {
        float c[8][4];
        #pragma unroll
        for (int nt = 0; nt < 8; nt++)
            #pragma unroll
            for (int i = 0; i < 4; i++) c[nt][i] = 0.f;
        const __half* A = aP2 + wid * 16 * KP2;
        #pragma unroll
        for (int ks = 0; ks < 3; ks++) {
            uint32_t a[4];
            ldA(a, A, KP2, fg, tig, ks * 16);
            #pragma unroll
            for (int nt = 0; nt < 8; nt++) {
                const __half* B = w2lS + (nt * 8 + fg) * KP2 + ks * 16 + tig * 2;
                uint32_t b0 = *(const uint32_t*)B;
                uint32_t b1 = *(const uint32_t*)(B + 8);
                mma16816(c[nt], a, b0, b1);
            }
        }
        // epilogue: celu + b2l -> segment atomics (rows sorted by seg)
        int row0 = wid * 16 + fg;
        int s0 = sseg[row0], s2 = sseg[row0 + 8];
        #pragma unroll
        for (int nt = 0; nt < 8; nt++) {
            int o = nt * 8 + tig * 2;
            atomicAdd(&agg2T[o * 36 + s0],       celu1(c[nt][0] + b2lS[o]));
            atomicAdd(&agg2T[(o + 1) * 36 + s0], celu1(c[nt][1] + b2lS[o + 1]));
            atomicAdd(&agg2T[o * 36 + s2],       celu1(c[nt][2] + b2lS[o]));
            atomicAdd(&agg2T[(o + 1) * 36 + s2], celu1(c[nt][3] + b2lS[o + 1]));
        }
    }
    __syncthreads();

    // ---- normalize + pack aF2[32][64] fp16 (cols 64..71 pad unread) ----
    for (int i = t; i < 2048; i += 256) {
        int s = i >> 6, j = i & 63;
        float inv = 1.f / fmaxf((float)cnt2i[s], 1.f);
        aF2[s * KF2 + j] = __float2half(agg2T[j * 36 + s] * inv);
    }
    __syncthreads();

    // ---- F2 HMMA: C[32x128] = aF2[32x64] @ W2g^T ----
    {
        int rt = wid >> 2, nr = wid & 3;
        float c[4][4];
        #pragma unroll
        for (int nt = 0; nt < 4; nt++)
            #pragma unroll
            for (int i = 0; i < 4; i++) c[nt][i] = 0.f;
        const __half* A = aF2 + rt * 16 * KF2;
        #pragma unroll
        for (int ks = 0; ks < 4; ks++) {
            uint32_t a[4];
            ldA(a, A, KF2, fg, tig, ks * 16);
            #pragma unroll
            for (int nt = 0; nt < 4; nt++) {
                const __half* B = w2gS + (nr * 32 + nt * 8 + fg) * KF2 + ks * 16 + tig * 2;
                uint32_t b0 = *(const uint32_t*)B;
                uint32_t b1 = *(const uint32_t*)(B + 8);
                mma16816(c[nt], a, b0, b1);
            }
        }
        // epilogue: celu + b2g -> aP3 fp16
        int srow0 = rt * 16 + fg;
        #pragma unroll
        for (int nt = 0; nt < 4; nt++) {
            int o = nr * 32 + nt * 8 + tig * 2;
            *(__half2*)&aP3[srow0 * KP3 + o] =
                __floats2half2_rn(celu1(c[nt][0] + b2gS[o]), celu1(c[nt][1] + b2gS[o + 1]));
            *(__half2*)&aP3[(srow0 + 8) * KP3 + o] =
                __floats2half2_rn(celu1(c[nt][2] + b2gS[o]), celu1(c[nt][3] + b2gS[o + 1]));
        }
    }
    __syncthreads();

    // ---- P3 HMMA: C[32x128] = aP3[32x128] @ W3l^T(rows 0..127) ----
    {
        int rt = wid >> 2, nr = wid & 3;
        float c[4][4];
        #pragma unroll
        for (int nt = 0; nt < 4; nt++)
            #pragma unroll
            for (int i = 0; i < 4; i++) c[nt][i] = 0.f;
        const __half* A = aP3 + rt * 16 * KP3;
        #pragma unroll
        for (int ks = 0; ks < 8; ks++) {
            uint32_t a[4];
            ldA(a, A, KP3, fg, tig, ks * 16);
            #pragma unroll
            for (int nt = 0; nt < 4; nt++) {
                const __half* B = w3lS + (nr * 32 + nt * 8 + fg) * KP3 + ks * 16 + tig * 2;
                uint32_t b0 = *(const uint32_t*)B;
                uint32_t b1 = *(const uint32_t*)(B + 8);
                mma16816(c[nt], a, b0, b1);
            }
        }
        __syncthreads();   // agg2T (same region as P3tmp) fully consumed; safe to overwrite
        // epilogue: + pos2-part + b3l, celu -> P3tmp[32][133]
        int s0 = rt * 16 + fg, s2 = s0 + 8;
        float px0 = pos2L[s0 * 3], py0 = pos2L[s0 * 3 + 1], pz0 = pos2L[s0 * 3 + 2];
        float px2 = pos2L[s2 * 3], py2 = pos2L[s2 * 3 + 1], pz2 = pos2L[s2 * 3 + 2];
        #pragma unroll
        for (int nt = 0; nt < 4; nt++) {
            int o = nr * 32 + nt * 8 + tig * 2;
            #pragma unroll
            for (int oi = 0; oi < 2; oi++) {
                int oo = o + oi;
                float pp0 = px0 * W3P[oo] + py0 * W3P[128 + oo] + pz0 * W3P[256 + oo];
                float pp2 = px2 * W3P[oo] + py2 * W3P[128 + oo] + pz2 * W3P[256 + oo];
                P3tmp[s0 * 133 + oo] = celu1(c[nt][oi] + pp0 + b3lS[oo]);
                P3tmp[s2 * 133 + oo] = celu1(c[nt][2 + oi] + pp2 + b3lS[oo]);
            }
        }
    }
    __syncthreads();

    if (t < 128) {
        float sum = 0.f;
        #pragma unroll 8
        for (int s = 0; s < 32; s++) sum += P3tmp[s * 133 + t];
        g_agg3m[g * 128 + t] = sum * (1.f / 32.f);
    }
}

// ---------------------------------------------------------------------------
// Tail (unchanged from R7): GPB=8, 512 threads, K-split halves.
// ---------------------------------------------------------------------------
#define GPB 8
__global__ __launch_bounds__(512) void tail_kernel(
    const float* __restrict__ W3g, const float* __restrict__ b3g,
    const float* __restrict__ Wlin, const float* __restrict__ blin,
    const float* __restrict__ eps, float* __restrict__ out)
{
    __shared__ __align__(16) float sAT[128 * GPB];
    __shared__ __align__(16) float sP[512 * GPB];
    __shared__ __align__(16) float sFT[256 * GPB];
    __shared__ __align__(16) float sO[256 * GPB];

    const int t    = threadIdx.x;
    const int o    = t & 255;
    const int half = t >> 8;
    const int g0   = blockIdx.x * GPB;

    for (int i = t; i < 128 * GPB; i += 512) {
        int j = i >> 3, gg = i & 7;
        sAT[j * 8 + gg] = g_agg3m[(g0 + gg) * 128 + j];
    }
    __syncthreads();

    {
        float acc[8];
        #pragma unroll
        for (int gg = 0; gg < 8; gg++) acc[gg] = 0.f;
        const int jb = half * 64;
        #pragma unroll 4
        for (int jj = 0; jj < 64; jj++) {
            const int j = jb + jj;
            const float w = W3g[j * 256 + o];
            float4 a0 = *(const float4*)&sAT[j * 8];
            float4 a1 = *(const float4*)&sAT[j * 8 + 4];
            acc[0] += a0.x * w; acc[1] += a0.y * w; acc[2] += a0.z * w; acc[3] += a0.w * w;
            acc[4] += a1.x * w; acc[5] += a1.y * w; acc[6] += a1.z * w; acc[7] += a1.w * w;
        }
        #pragma unroll
        for (int gg = 0; gg < 8; gg++) sP[t * 8 + gg] = acc[gg];
    }
    __syncthreads();
    if (half == 0) {
        const float bo = b3g[o];
        #pragma unroll
        for (int gg = 0; gg < 8; gg++) {
            float v = celu1(sP[o * 8 + gg] + sP[(256 + o) * 8 + gg] + bo);
            sFT[o * 8 + gg] = v;
            out[786432 + (size_t)(g0 + gg) * 256 + o] = v;
        }
    }
    __syncthreads();

    {
        float acc[8];
        #pragma unroll
        for (int gg = 0; gg < 8; gg++) acc[gg] = 0.f;
        const int jb = half * 128;
        #pragma unroll 4
        for (int jj = 0; jj < 128; jj++) {
            const int j = jb + jj;
            const float w = Wlin[j * 256 + o];
            float4 a0 = *(const float4*)&sFT[j * 8];
            float4 a1 = *(const float4*)&sFT[j * 8 + 4];
            acc[0] += a0.x * w; acc[1] += a0.y * w; acc[2] += a0.z * w; acc[3] += a0.w * w;
            acc[4] += a1.x * w; acc[5] += a1.y * w; acc[6] += a1.z * w; acc[7] += a1.w * w;
        }
        #pragma unroll
        for (int gg = 0; gg < 8; gg++) sP[t * 8 + gg] = acc[gg];
    }
    __syncthreads();
    if (half == 0) {
        const float bo = blin[o];
        #pragma unroll
        for (int gg = 0; gg < 8; gg++)
            sO[o * 8 + gg] = sP[o * 8 + gg] + sP[(256 + o) * 8 + gg] + bo;
    }
    __syncthreads();

    for (int i = t; i < 128 * GPB; i += 512) {
        int gg = i >> 7, c = i & 127;
        int gid = g0 + gg;
        float mu = sO[c * 8 + gg];
        float sg = sO[(128 + c) * 8 + gg];
        float sigma = (sg > 20.f) ? sg : log1pf(expf(sg));
        float z = mu + sigma * eps[gid * 128 + c];
        if (c < 64) out[(size_t)gid * 64 + c] = z;
        else        out[131072 + (size_t)gid * 64 + (c - 64)] = z;
        out[262144 + (size_t)gid * 128 + c] = mu;
        out[524288 + (size_t)gid * 128 + c] = sigma;
    }
}

extern "C" void kernel_launch(void* const* d_in, const int* in_sizes, int n_in,
                              void* d_out, int out_size)
{
    (void)in_sizes; (void)n_in; (void)out_size;
    const float* rgb  = (const float*)d_in[0];
    const float* pos  = (const float*)d_in[1];
    const float* pos1 = (const float*)d_in[2];
    const float* pos2 = (const float*)d_in[3];
    const int*   idx0 = (const int*)d_in[4];
    const int*   idx1 = (const int*)d_in[5];
    // d_in[6] (out_index2) unused: structure implied
    const float* eps  = (const float*)d_in[7];
    const float* W1l  = (const float*)d_in[8];
    const float* b1l  = (const float*)d_in[9];
    const float* W1g  = (const float*)d_in[10];
    const float* b1g  = (const float*)d_in[11];
    const float* W2l  = (const float*)d_in[12];
    const float* b2l  = (const float*)d_in[13];
    const float* W2g  = (const float*)d_in[14];
    const float* b2g  = (const float*)d_in[15];
    const float* W3l  = (const float*)d_in[16];
    const float* b3l  = (const float*)d_in[17];
    const float* W3g  = (const float*)d_in[18];
    const float* b3g  = (const float*)d_in[19];
    const float* Wlin = (const float*)d_in[20];
    const float* blin = (const float*)d_in[21];
    float* out = (float*)d_out;

    cudaFuncSetAttribute(glimpse_kernel, cudaFuncAttributeMaxDynamicSharedMemorySize, SMEM_BYTES);

    prep_kernel<<<119, 256>>>(W2l, W2g, W3l);
    glimpse_kernel<<<NG, 256, SMEM_BYTES>>>(rgb, pos, pos1, pos2, idx0, idx1,
                                            W1l, b1l, W1g, b1g, b2l, b2g, W3l, b3l);
    tail_kernel<<<NG / GPB, 512>>>(W3g, b3g, Wlin, blin, eps, out);
}

// round 11
// speedup vs baseline: 1.3558x; 1.3558x over previous
#include <cuda_runtime.h>
#include <cuda_fp16.h>
#include <cstdint>

// Problem constants
#define NG        2048
#define NPG       512
#define CPG       128
#define CPG2      32

// Padded k-strides (halves). stride/2 banks ≡ 4 (mod 8) -> conflict-free frag loads
#define KP2 56    // P2 A + W2l  (K used = 48)
#define KF2 72    // F2 A + W2g  (K used = 64)
#define KP3 136   // P3 A + W3l  (K used = 128)

__device__ __forceinline__ float celu1(float x) {
    return fmaxf(x, 0.f) + (__expf(fminf(x, 0.f)) - 1.f);
}

// ---------------------------------------------------------------------------
// Global scratch (weights stay in L2; every CTA reads the same 59 KB)
// ---------------------------------------------------------------------------
__device__ float g_agg3m[NG * 128];
__device__ __align__(16) __half g_w2lH[64 * KP2];     //  7KB  W2l^T [n=64][k=56]
__device__ __align__(16) __half g_w2gH[128 * KF2];    // 18KB  W2g^T [n=128][k=72]
__device__ __align__(16) __half g_w3lH[128 * KP3];    // 34KB  W3l^T [n=128][k=136]

// ---------------------------------------------------------------------------
// HMMA m16n8k16 helpers (fp16 in, fp32 accum) — sm_103-legal PTX
// ---------------------------------------------------------------------------
__device__ __forceinline__ void mma16816(float* c, const uint32_t* a, uint32_t b0, uint32_t b1) {
    asm volatile("mma.sync.aligned.m16n8k16.row.col.f32.f16.f16.f32 "
        "{%0,%1,%2,%3}, {%4,%5,%6,%7}, {%8,%9}, {%0,%1,%2,%3};"
        : "+f"(c[0]), "+f"(c[1]), "+f"(c[2]), "+f"(c[3])
        : "r"(a[0]), "r"(a[1]), "r"(a[2]), "r"(a[3]), "r"(b0), "r"(b1));
}
__device__ __forceinline__ void ldA(uint32_t* a, const __half* A, int stride, int g, int tig, int k0) {
    a[0] = *(const uint32_t*)(A + g * stride + k0 + tig * 2);
    a[1] = *(const uint32_t*)(A + (g + 8) * stride + k0 + tig * 2);
    a[2] = *(const uint32_t*)(A + g * stride + k0 + 8 + tig * 2);
    a[3] = *(const uint32_t*)(A + (g + 8) * stride + k0 + 8 + tig * 2);
}

// ---------------------------------------------------------------------------
// Prep kernel: fp16 transposed padded weight images (once per launch)
// ---------------------------------------------------------------------------
__global__ void prep_kernel(const float* __restrict__ W2l,
                            const float* __restrict__ W2g,
                            const float* __restrict__ W3l)
{
    int i = blockIdx.x * 256 + threadIdx.x;
    const int N0 = 64 * KP2, N1 = 128 * KF2, N2 = 128 * KP3;
    if (i < N0) {
        int n = i / KP2, k = i % KP2;
        g_w2lH[i] = __float2half(k < 35 ? W2l[k * 64 + n] : 0.f);
    } else if (i < N0 + N1) {
        int j = i - N0; int n = j / KF2, k = j % KF2;
        g_w2gH[j] = __float2half(k < 64 ? W2g[k * 128 + n] : 0.f);
    } else if (i < N0 + N1 + N2) {
        int j = i - N0 - N1; int n = j / KP3, k = j % KP3;
        g_w3lH[j] = __float2half(k < 128 ? W3l[k * 128 + n] : 0.f);
    }
}

// ---------------------------------------------------------------------------
// Shared-memory float-index layout (dynamic, 12592 floats = 50368 B -> occ 4)
// ---------------------------------------------------------------------------
#define F_POS1   0       // 384
#define F_POS2   384     // 96
#define F_W1L    480     // 64
#define F_B1L    544     // 16
#define F_W1G    560     // 512
#define F_B1G    1072    // 32
#define F_B2L    1104    // 64
#define F_B2G    1168    // 128
#define F_B3L    1296    // 128
#define F_W3P    1424    // 384 (W3l rows 128..130)
#define I_S1     1808    // 128 int
#define I_SLOT   1936
#define I_SSEG   2064
#define I_OFF1   2192
#define I_OFF1F  2320
#define I_OFF2F  2448    // 32
#define I_CNT1   2480    // 128
#define I_CNT2   2608    // 32
#define F_STAGE  2640    // 4256: stX/stP/stS/plist -> agg2T[64][36] -> P3tmp[32][133]
#define F_AGG1T  6896    // 2112 ([16][132])
#define F_AH     9008    // 3584: aP2[128][56]h -> aF2[32][72]h @+0, aP3[32][136]h @+1152
#define F_TOT    12592
#define SMEM_BYTES (F_TOT * 4)

__global__ __launch_bounds__(256, 4) void glimpse_kernel(
    const float* __restrict__ rgb,  const float* __restrict__ pos,
    const float* __restrict__ pos1, const float* __restrict__ pos2,
    const int* __restrict__ idx0, const int* __restrict__ idx1,
    const float* __restrict__ W1l, const float* __restrict__ b1l,
    const float* __restrict__ W1g, const float* __restrict__ b1g,
    const float* __restrict__ b2l, const float* __restrict__ b2g,
    const float* __restrict__ W3l, const float* __restrict__ b3l)
{
    extern __shared__ __align__(16) float sm[];
    int* smi = (int*)sm;

    float* pos1L = sm + F_POS1;
    float* pos2L = sm + F_POS2;
    float* W1lS  = sm + F_W1L;
    float* b1lS  = sm + F_B1L;
    float* W1gS  = sm + F_W1G;
    float* b1gS  = sm + F_B1G;
    float* b2lS  = sm + F_B2L;
    float* b2gS  = sm + F_B2G;
    float* b3lS  = sm + F_B3L;
    float* W3P   = sm + F_W3P;
    int*   s1    = smi + I_S1;
    int*   slot  = smi + I_SLOT;
    int*   sseg  = smi + I_SSEG;
    int*   off1  = smi + I_OFF1;
    int*   off1f = smi + I_OFF1F;
    int*   off2f = smi + I_OFF2F;
    int*   cnt1i = smi + I_CNT1;
    int*   cnt2i = smi + I_CNT2;
    float* stX   = sm + F_STAGE;
    float* stPx  = sm + F_STAGE + 512;
    float* stPy  = sm + F_STAGE + 1024;
    float* stPz  = sm + F_STAGE + 1536;
    int*   stS   = smi + F_STAGE + 2048;
    int*   plist = smi + F_STAGE + 2560;
    float* agg2T = sm + F_STAGE;              // [64][36], after staging dies
    float* P3tmp = sm + F_STAGE;              // [32][133], after agg2T dies
    float* agg1T = sm + F_AGG1T;              // [16][132]
    __half* aP2  = (__half*)(sm + F_AH);      // [128][KP2]
    __half* aF2  = (__half*)(sm + F_AH);      // [32][KF2]   (aP2 dead)
    __half* aP3  = (__half*)(sm + F_AH + 1152); // [32][KP3]

    const int t = threadIdx.x;
    const int wid = t >> 5;
    const int lane = t & 31;
    const int g = blockIdx.x;
    const int fg = lane >> 2;     // fragment row group 0..7
    const int tig = lane & 3;     // thread-in-group

    // ---- block 0: loads + zeros (NO weight copies anymore) ----
    for (int i = t; i < 384; i += 256) pos1L[i] = pos1[g * 384 + i];
    for (int i = t; i < 96;  i += 256) pos2L[i] = pos2[g * 96 + i];
    if (t < 64) { W1lS[t] = W1l[t]; b2lS[t] = b2l[t]; }
    if (t < 16) b1lS[t] = b1l[t];
    for (int i = t; i < 512; i += 256) W1gS[i] = W1g[i];
    if (t < 32) b1gS[t] = b1g[t];
    for (int i = t; i < 128; i += 256) { b2gS[i] = b2g[i]; b3lS[i] = b3l[i]; cnt1i[i] = 0; }
    for (int i = t; i < 384; i += 256) W3P[i] = W3l[128 * 128 + i];
    if (t < 32) cnt2i[t] = 0;
    for (int i = t; i < 2112; i += 256) agg1T[i] = 0.f;
    __syncthreads();

    // ---- block 1: stage points + counts ----
    for (int p = t; p < 512; p += 256) {
        stX[p] = rgb[g * 512 + p];
        int s = (idx0[g * 512 + p] - g * CPG) & (CPG - 1);
        stS[p] = s;
        atomicAdd(&cnt1i[s], 1);
    }
    for (int i = t; i < 1536; i += 256) {
        float v = pos[g * 1536 + i];
        int p = i / 3, c = i - p * 3;
        if (c == 0) stPx[p] = v; else if (c == 1) stPy[p] = v; else stPz[p] = v;
    }
    if (t < 128) {
        int s = (idx1[g * 128 + t] - g * CPG2) & (CPG2 - 1);
        s1[t] = s;
        atomicAdd(&cnt2i[s], 1);
    }
    __syncthreads();

    // ---- block 2: prefix sums ----
    if (t < 32) {
        int carry = 0;
        for (int c = 0; c < 4; c++) {
            int v = cnt1i[c * 32 + t];
            int x = v;
            #pragma unroll
            for (int d = 1; d < 32; d <<= 1) {
                int y = __shfl_up_sync(0xffffffffu, x, d);
                if (t >= d) x += y;
            }
            int excl = x - v + carry;
            off1[c * 32 + t] = excl;
            off1f[c * 32 + t] = excl;
            carry += __shfl_sync(0xffffffffu, x, 31);
        }
    } else if (t < 64) {
        int ln = t - 32;
        int v = cnt2i[ln];
        int x = v;
        #pragma unroll
        for (int d = 1; d < 32; d <<= 1) {
            int y = __shfl_up_sync(0xffffffffu, x, d);
            if (ln >= d) x += y;
        }
        off2f[ln] = x - v;
    }
    __syncthreads();

    // ---- block 3: scatter sorted point list + row slots ----
    for (int p = t; p < 512; p += 256) {
        int s = stS[p];
        int pp = atomicAdd(&off1f[s], 1);
        plist[pp] = p;
    }
    if (t < 128) {
        int s = s1[t];
        int q = atomicAdd(&off2f[s], 1);
        slot[t] = q;
        sseg[q] = s;
    }
    __syncthreads();

    // ---- block 4: phase-1 accumulate + rel/pad rows into aP2 ----
    {
        int s = t >> 1, jb = (t & 1) * 8;
        int cnt = cnt1i[s], base = off1[s];
        float acc[8];
        #pragma unroll
        for (int j = 0; j < 8; j++) acc[j] = 0.f;
        const float c1x = pos1L[s * 3 + 0], c1y = pos1L[s * 3 + 1], c1z = pos1L[s * 3 + 2];
        for (int e = 0; e < cnt; e++) {
            int p = plist[base + e];
            float x0 = stX[p];
            float rx = stPx[p] - c1x, ry = stPy[p] - c1y, rz = stPz[p] - c1z;
            #pragma unroll
            for (int j = 0; j < 8; j++) {
                float h = b1lS[jb + j] + x0 * W1lS[jb + j] + rx * W1lS[16 + jb + j]
                        + ry * W1lS[32 + jb + j] + rz * W1lS[48 + jb + j];
                acc[j] += celu1(h);
            }
        }
        float inv = 1.f / (float)max(cnt, 1);
        #pragma unroll
        for (int j = 0; j < 8; j++) agg1T[(jb + j) * 132 + s] = acc[j] * inv;
    }
    if (t < 128) {
        int r = t, q = slot[r], s = s1[r];
        __half* row = aP2 + q * KP2;
        row[32] = __float2half(pos1L[r * 3 + 0] - pos2L[s * 3 + 0]);
        row[33] = __float2half(pos1L[r * 3 + 1] - pos2L[s * 3 + 1]);
        row[34] = __float2half(pos1L[r * 3 + 2] - pos2L[s * 3 + 2]);
        #pragma unroll
        for (int k = 35; k < 48; k++) row[k] = __float2half(0.f);
    }
    __syncthreads();

    // ---- f1 GEMM (scalar, tiny) -> aP2 cols 0..31 ; also zero agg2T ----
    {
        int ob = t & 7, rb = t >> 3;
        int r0 = rb * 4, o0 = ob * 4;
        float acc[4][4];
        #pragma unroll
        for (int ri = 0; ri < 4; ri++)
            #pragma unroll
            for (int oi = 0; oi < 4; oi++) acc[ri][oi] = b1gS[o0 + oi];
        #pragma unroll
        for (int j = 0; j < 16; j++) {
            float4 x = *(const float4*)&agg1T[j * 132 + r0];
            float4 w = *(const float4*)&W1gS[j * 32 + o0];
            float xa[4] = {x.x, x.y, x.z, x.w};
            float wa[4] = {w.x, w.y, w.z, w.w};
            #pragma unroll
            for (int ri = 0; ri < 4; ri++)
                #pragma unroll
                for (int oi = 0; oi < 4; oi++) acc[ri][oi] += xa[ri] * wa[oi];
        }
        #pragma unroll
        for (int ri = 0; ri < 4; ri++) {
            int q = slot[r0 + ri];
            *(__half2*)&aP2[q * KP2 + o0]     = __floats2half2_rn(celu1(acc[ri][0]), celu1(acc[ri][1]));
            *(__half2*)&aP2[q * KP2 + o0 + 2] = __floats2half2_rn(celu1(acc[ri][2]), celu1(acc[ri][3]));
        }
    }
    for (int i = t; i < 64 * 36; i += 256) agg2T[i] = 0.f;   // staging is dead now
    __syncthreads();

    // ---- P2 HMMA: C[128x64] = aP2[128x48] @ W2l^T (B frags from L2) ----
    {
        float c[8][4];
        #pragma unroll
        for (int nt = 0; nt < 8; nt++)
            #pragma unroll
            for (int i = 0; i < 4; i++) c[nt][i] = 0.f;
        const __half* A = aP2 + wid * 16 * KP2;
        #pragma unroll
        for (int ks = 0; ks < 3; ks++) {
            uint32_t a[4];
            ldA(a, A, KP2, fg, tig, ks * 16);
            #pragma unroll
            for (int nt = 0; nt < 8; nt++) {
                const __half* B = g_w2lH + (nt * 8 + fg) * KP2 + ks * 16 + tig * 2;
                uint32_t b0 = __ldg((const uint32_t*)B);
                uint32_t b1 = __ldg((const uint32_t*)(B + 8));
                mma16816(c[nt], a, b0, b1);
            }
        }
        int row0 = wid * 16 + fg;
        int s0 = sseg[row0], s2 = sseg[row0 + 8];
        #pragma unroll
        for (int nt = 0; nt < 8; nt++) {
            int o = nt * 8 + tig * 2;
            atomicAdd(&agg2T[o * 36 + s0],       celu1(c[nt][0] + b2lS[o]));
            atomicAdd(&agg2T[(o + 1) * 36 + s0], celu1(c[nt][1] + b2lS[o + 1]));
            atomicAdd(&agg2T[o * 36 + s2],       celu1(c[nt][2] + b2lS[o]));
            atomicAdd(&agg2T[(o + 1) * 36 + s2], celu1(c[nt][3] + b2lS[o + 1]));
        }
    }
    __syncthreads();

    // ---- normalize + pack aF2[32][64] fp16 ----
    for (int i = t; i < 2048; i += 256) {
        int s = i >> 6, j = i & 63;
        float inv = 1.f / fmaxf((float)cnt2i[s], 1.f);
        aF2[s * KF2 + j] = __float2half(agg2T[j * 36 + s] * inv);
    }
    __syncthreads();

    // ---- F2 HMMA: C[32x128] = aF2[32x64] @ W2g^T ----
    {
        int rt = wid >> 2, nr = wid & 3;
        float c[4][4];
        #pragma unroll
        for (int nt = 0; nt < 4; nt++)
            #pragma unroll
            for (int i = 0; i < 4; i++) c[nt][i] = 0.f;
        const __half* A = aF2 + rt * 16 * KF2;
        #pragma unroll
        for (int ks = 0; ks < 4; ks++) {
            uint32_t a[4];
            ldA(a, A, KF2, fg, tig, ks * 16);
            #pragma unroll
            for (int nt = 0; nt < 4; nt++) {
                const __half* B = g_w2gH + (nr * 32 + nt * 8 + fg) * KF2 + ks * 16 + tig * 2;
                uint32_t b0 = __ldg((const uint32_t*)B);
                uint32_t b1 = __ldg((const uint32_t*)(B + 8));
                mma16816(c[nt], a, b0, b1);
            }
        }
        int srow0 = rt * 16 + fg;
        #pragma unroll
        for (int nt = 0; nt < 4; nt++) {
            int o = nr * 32 + nt * 8 + tig * 2;
            *(__half2*)&aP3[srow0 * KP3 + o] =
                __floats2half2_rn(celu1(c[nt][0] + b2gS[o]), celu1(c[nt][1] + b2gS[o + 1]));
            *(__half2*)&aP3[(srow0 + 8) * KP3 + o] =
                __floats2half2_rn(celu1(c[nt][2] + b2gS[o]), celu1(c[nt][3] + b2gS[o + 1]));
        }
    }
    __syncthreads();

    // ---- P3 HMMA: C[32x128] = aP3[32x128] @ W3l^T(rows 0..127) ----
    {
        int rt = wid >> 2, nr = wid & 3;
        float c[4][4];
        #pragma unroll
        for (int nt = 0; nt < 4; nt++)
            #pragma unroll
            for (int i = 0; i < 4; i++) c[nt][i] = 0.f;
        const __half* A = aP3 + rt * 16 * KP3;
        #pragma unroll
        for (int ks = 0; ks < 8; ks++) {
            uint32_t a[4];
            ldA(a, A, KP3, fg, tig, ks * 16);
            #pragma unroll
            for (int nt = 0; nt < 4; nt++) {
                const __half* B = g_w3lH + (nr * 32 + nt * 8 + fg) * KP3 + ks * 16 + tig * 2;
                uint32_t b0 = __ldg((const uint32_t*)B);
                uint32_t b1 = __ldg((const uint32_t*)(B + 8));
                mma16816(c[nt], a, b0, b1);
            }
        }
        __syncthreads();   // agg2T region fully consumed; safe to overwrite as P3tmp
        int s0 = rt * 16 + fg, s2 = s0 + 8;
        float px0 = pos2L[s0 * 3], py0 = pos2L[s0 * 3 + 1], pz0 = pos2L[s0 * 3 + 2];
        float px2 = pos2L[s2 * 3], py2 = pos2L[s2 * 3 + 1], pz2 = pos2L[s2 * 3 + 2];
        #pragma unroll
        for (int nt = 0; nt < 4; nt++) {
            int o = nr * 32 + nt * 8 + tig * 2;
            #pragma unroll
            for (int oi = 0; oi < 2; oi++) {
                int oo = o + oi;
                float pp0 = px0 * W3P[oo] + py0 * W3P[128 + oo] + pz0 * W3P[256 + oo];
                float pp2 = px2 * W3P[oo] + py2 * W3P[128 + oo] + pz2 * W3P[256 + oo];
                P3tmp[s0 * 133 + oo] = celu1(c[nt][oi] + pp0 + b3lS[oo]);
                P3tmp[s2 * 133 + oo] = celu1(c[nt][2 + oi] + pp2 + b3lS[oo]);
            }
        }
    }
    __syncthreads();

    if (t < 128) {
        float sum = 0.f;
        #pragma unroll 8
        for (int s = 0; s < 32; s++) sum += P3tmp[s * 133 + t];
        g_agg3m[g * 128 + t] = sum * (1.f / 32.f);
    }
}

// ---------------------------------------------------------------------------
// Tail (unchanged): GPB=8, 512 threads, K-split halves.
// ---------------------------------------------------------------------------
#define GPB 8
__global__ __launch_bounds__(512) void tail_kernel(
    const float* __restrict__ W3g, const float* __restrict__ b3g,
    const float* __restrict__ Wlin, const float* __restrict__ blin,
    const float* __restrict__ eps, float* __restrict__ out)
{
    __shared__ __align__(16) float sAT[128 * GPB];
    __shared__ __align__(16) float sP[512 * GPB];
    __shared__ __align__(16) float sFT[256 * GPB];
    __shared__ __align__(16) float sO[256 * GPB];

    const int t    = threadIdx.x;
    const int o    = t & 255;
    const int half = t >> 8;
    const int g0   = blockIdx.x * GPB;

    for (int i = t; i < 128 * GPB; i += 512) {
        int j = i >> 3, gg = i & 7;
        sAT[j * 8 + gg] = g_agg3m[(g0 + gg) * 128 + j];
    }
    __syncthreads();

    {
        float acc[8];
        #pragma unroll
        for (int gg = 0; gg < 8; gg++) acc[gg] = 0.f;
        const int jb = half * 64;
        #pragma unroll 4
        for (int jj = 0; jj < 64; jj++) {
            const int j = jb + jj;
            const float w = W3g[j * 256 + o];
            float4 a0 = *(const float4*)&sAT[j * 8];
            float4 a1 = *(const float4*)&sAT[j * 8 + 4];
            acc[0] += a0.x * w; acc[1] += a0.y * w; acc[2] += a0.z * w; acc[3] += a0.w * w;
            acc[4] += a1.x * w; acc[5] += a1.y * w; acc[6] += a1.z * w; acc[7] += a1.w * w;
        }
        #pragma unroll
        for (int gg = 0; gg < 8; gg++) sP[t * 8 + gg] = acc[gg];
    }
    __syncthreads();
    if (half == 0) {
        const float bo = b3g[o];
        #pragma unroll
        for (int gg = 0; gg < 8; gg++) {
            float v = celu1(sP[o * 8 + gg] + sP[(256 + o) * 8 + gg] + bo);
            sFT[o * 8 + gg] = v;
            out[786432 + (size_t)(g0 + gg) * 256 + o] = v;
        }
    }
    __syncthreads();

    {
        float acc[8];
        #pragma unroll
        for (int gg = 0; gg < 8; gg++) acc[gg] = 0.f;
        const int jb = half * 128;
        #pragma unroll 4
        for (int jj = 0; jj < 128; jj++) {
            const int j = jb + jj;
            const float w = Wlin[j * 256 + o];
            float4 a0 = *(const float4*)&sFT[j * 8];
            float4 a1 = *(const float4*)&sFT[j * 8 + 4];
            acc[0] += a0.x * w; acc[1] += a0.y * w; acc[2] += a0.z * w; acc[3] += a0.w * w;
            acc[4] += a1.x * w; acc[5] += a1.y * w; acc[6] += a1.z * w; acc[7] += a1.w * w;
        }
        #pragma unroll
        for (int gg = 0; gg < 8; gg++) sP[t * 8 + gg] = acc[gg];
    }
    __syncthreads();
    if (half == 0) {
        const float bo = blin[o];
        #pragma unroll
        for (int gg = 0; gg < 8; gg++)
            sO[o * 8 + gg] = sP[o * 8 + gg] + sP[(256 + o) * 8 + gg] + bo;
    }
    __syncthreads();

    for (int i = t; i < 128 * GPB; i += 512) {
        int gg = i >> 7, c = i & 127;
        int gid = g0 + gg;
        float mu = sO[c * 8 + gg];
        float sg = sO[(128 + c) * 8 + gg];
        float sigma = (sg > 20.f) ? sg : log1pf(expf(sg));
        float z = mu + sigma * eps[gid * 128 + c];
        if (c < 64) out[(size_t)gid * 64 + c] = z;
        else        out[131072 + (size_t)gid * 64 + (c - 64)] = z;
        out[262144 + (size_t)gid * 128 + c] = mu;
        out[524288 + (size_t)gid * 128 + c] = sigma;
    }
}

extern "C" void kernel_launch(void* const* d_in, const int* in_sizes, int n_in,
                              void* d_out, int out_size)
{
    (void)in_sizes; (void)n_in; (void)out_size;
    const float* rgb  = (const float*)d_in[0];
    const float* pos  = (const float*)d_in[1];
    const float* pos1 = (const float*)d_in[2];
    const float* pos2 = (const float*)d_in[3];
    const int*   idx0 = (const int*)d_in[4];
    const int*   idx1 = (const int*)d_in[5];
    // d_in[6] (out_index2) unused: structure implied
    const float* eps  = (const float*)d_in[7];
    const float* W1l  = (const float*)d_in[8];
    const float* b1l  = (const float*)d_in[9];
    const float* W1g  = (const float*)d_in[10];
    const float* b1g  = (const float*)d_in[11];
    const float* W2l  = (const float*)d_in[12];
    const float* b2l  = (const float*)d_in[13];
    const float* W2g  = (const float*)d_in[14];
    const float* b2g  = (const float*)d_in[15];
    const float* W3l  = (const float*)d_in[16];
    const float* b3l  = (const float*)d_in[17];
    const float* W3g  = (const float*)d_in[18];
    const float* b3g  = (const float*)d_in[19];
    const float* Wlin = (const float*)d_in[20];
    const float* blin = (const float*)d_in[21];
    float* out = (float*)d_out;

    cudaFuncSetAttribute(glimpse_kernel, cudaFuncAttributeMaxDynamicSharedMemorySize, SMEM_BYTES);

    prep_kernel<<<119, 256>>>(W2l, W2g, W3l);
    glimpse_kernel<<<NG, 256, SMEM_BYTES>>>(rgb, pos, pos1, pos2, idx0, idx1,
                                            W1l, b1l, W1g, b1g, b2l, b2g, W3l, b3l);
    tail_kernel<<<NG / GPB, 512>>>(W3g, b3g, Wlin, blin, eps, out);
}

// round 16
// speedup vs baseline: 1.4710x; 1.0850x over previous
#include <cuda_runtime.h>
#include <cuda_fp16.h>
#include <cstdint>

// Problem constants
#define NG        2048
#define NPG       512
#define CPG       128
#define CPG2      32

// Padded k-strides (halves). stride/2 banks ≡ 4 (mod 8) -> conflict-free frag loads
#define KP2 56    // P2 A + W2l  (K used = 48)
#define KF2 72    // F2 A + W2g  (K used = 64)
#define KP3 136   // P3 A + W3l  (K used = 128); also tail GEMM1 (K=128)
#define KLN 264   // tail GEMM2  (K used = 256)

__device__ __forceinline__ float celu1(float x) {
    return fmaxf(x, 0.f) + (__expf(fminf(x, 0.f)) - 1.f);
}

// ---------------------------------------------------------------------------
// Global scratch (weights stay in L2; shared by all CTAs)
// ---------------------------------------------------------------------------
__device__ __align__(16) __half g_a3H[NG * KP3];      // 557KB glimpse result, fp16 A-image
__device__ __align__(16) __half g_w2lH[64 * KP2];     //  7KB  W2l^T [n=64][k=56]
__device__ __align__(16) __half g_w2gH[128 * KF2];    // 18KB  W2g^T [n=128][k=72]
__device__ __align__(16) __half g_w3lH[128 * KP3];    // 34KB  W3l^T [n=128][k=136]
__device__ __align__(16) __half g_w3gT[256 * KP3];    // 70KB  W3g^T [n=256][k=136]
__device__ __align__(16) __half g_wlinT[256 * KLN];   // 135KB Wlin^T [n=256][k=264]

// ---------------------------------------------------------------------------
// HMMA m16n8k16 helpers (fp16 in, fp32 accum) — sm_103-legal PTX
// ---------------------------------------------------------------------------
__device__ __forceinline__ void mma16816(float* c, const uint32_t* a, uint32_t b0, uint32_t b1) {
    asm volatile("mma.sync.aligned.m16n8k16.row.col.f32.f16.f16.f32 "
        "{%0,%1,%2,%3}, {%4,%5,%6,%7}, {%8,%9}, {%0,%1,%2,%3};"
        : "+f"(c[0]), "+f"(c[1]), "+f"(c[2]), "+f"(c[3])
        : "r"(a[0]), "r"(a[1]), "r"(a[2]), "r"(a[3]), "r"(b0), "r"(b1));
}
__device__ __forceinline__ void ldA(uint32_t* a, const __half* A, int stride, int g, int tig, int k0) {
    a[0] = *(const uint32_t*)(A + g * stride + k0 + tig * 2);
    a[1] = *(const uint32_t*)(A + (g + 8) * stride + k0 + tig * 2);
    a[2] = *(const uint32_t*)(A + g * stride + k0 + 8 + tig * 2);
    a[3] = *(const uint32_t*)(A + (g + 8) * stride + k0 + 8 + tig * 2);
}

// ---------------------------------------------------------------------------
// Prep kernel: fp16 transposed padded weight images (once per launch)
// ---------------------------------------------------------------------------
__global__ void prep_kernel(const float* __restrict__ W2l,
                            const float* __restrict__ W2g,
                            const float* __restrict__ W3l,
                            const float* __restrict__ W3g,
                            const float* __restrict__ Wlin)
{
    int i = blockIdx.x * 256 + threadIdx.x;
    const int N0 = 64 * KP2, N1 = 128 * KF2, N2 = 128 * KP3;
    const int N3 = 256 * KP3, N4 = 256 * KLN;
    if (i < N0) {
        int n = i / KP2, k = i % KP2;
        g_w2lH[i] = __float2half(k < 35 ? W2l[k * 64 + n] : 0.f);
    } else if (i < N0 + N1) {
        int j = i - N0; int n = j / KF2, k = j % KF2;
        g_w2gH[j] = __float2half(k < 64 ? W2g[k * 128 + n] : 0.f);
    } else if (i < N0 + N1 + N2) {
        int j = i - N0 - N1; int n = j / KP3, k = j % KP3;
        g_w3lH[j] = __float2half(k < 128 ? W3l[k * 128 + n] : 0.f);
    } else if (i < N0 + N1 + N2 + N3) {
        int j = i - N0 - N1 - N2; int n = j / KP3, k = j % KP3;
        g_w3gT[j] = __float2half(k < 128 ? W3g[k * 256 + n] : 0.f);
    } else if (i < N0 + N1 + N2 + N3 + N4) {
        int j = i - N0 - N1 - N2 - N3; int n = j / KLN, k = j % KLN;
        g_wlinT[j] = __float2half(k < 256 ? Wlin[k * 256 + n] : 0.f);
    }
}
#define PREP_ELEMS (64*KP2 + 128*KF2 + 128*KP3 + 256*KP3 + 256*KLN)

// ---------------------------------------------------------------------------
// Glimpse kernel smem layout (dynamic, 12592 floats = 50368 B -> occ 4)
// ---------------------------------------------------------------------------
#define F_POS1   0
#define F_POS2   384
#define F_W1L    480
#define F_B1L    544
#define F_W1G    560
#define F_B1G    1072
#define F_B2L    1104
#define F_B2G    1168
#define F_B3L    1296
#define F_W3P    1424
#define I_S1     1808
#define I_SLOT   1936
#define I_SSEG   2064
#define I_OFF1   2192
#define I_OFF1F  2320
#define I_OFF2F  2448
#define I_CNT1   2480
#define I_CNT2   2608
#define F_STAGE  2640
#define F_AGG1T  6896
#define F_AH     9008
#define F_TOT    12592
#define SMEM_BYTES (F_TOT * 4)

__global__ __launch_bounds__(256, 4) void glimpse_kernel(
    const float* __restrict__ rgb,  const float* __restrict__ pos,
    const float* __restrict__ pos1, const float* __restrict__ pos2,
    const int* __restrict__ idx0, const int* __restrict__ idx1,
    const float* __restrict__ W1l, const float* __restrict__ b1l,
    const float* __restrict__ W1g, const float* __restrict__ b1g,
    const float* __restrict__ b2l, const float* __restrict__ b2g,
    const float* __restrict__ W3l, const float* __restrict__ b3l)
{
    extern __shared__ __align__(16) float sm[];
    int* smi = (int*)sm;

    float* pos1L = sm + F_POS1;
    float* pos2L = sm + F_POS2;
    float* W1lS  = sm + F_W1L;
    float* b1lS  = sm + F_B1L;
    float* W1gS  = sm + F_W1G;
    float* b1gS  = sm + F_B1G;
    float* b2lS  = sm + F_B2L;
    float* b2gS  = sm + F_B2G;
    float* b3lS  = sm + F_B3L;
    float* W3P   = sm + F_W3P;
    int*   s1    = smi + I_S1;
    int*   slot  = smi + I_SLOT;
    int*   sseg  = smi + I_SSEG;
    int*   off1  = smi + I_OFF1;
    int*   off1f = smi + I_OFF1F;
    int*   off2f = smi + I_OFF2F;
    int*   cnt1i = smi + I_CNT1;
    int*   cnt2i = smi + I_CNT2;
    float* stX   = sm + F_STAGE;
    float* stPx  = sm + F_STAGE + 512;
    float* stPy  = sm + F_STAGE + 1024;
    float* stPz  = sm + F_STAGE + 1536;
    int*   stS   = smi + F_STAGE + 2048;
    int*   plist = smi + F_STAGE + 2560;
    float* agg2T = sm + F_STAGE;              // [64][36], after staging dies
    float* P3tmp = sm + F_STAGE;              // [32][133], after agg2T dies
    float* agg1T = sm + F_AGG1T;              // [16][132]
    __half* aP2  = (__half*)(sm + F_AH);      // [128][KP2]
    __half* aF2  = (__half*)(sm + F_AH);      // [32][KF2]   (aP2 dead)
    __half* aP3  = (__half*)(sm + F_AH + 1152); // [32][KP3]

    const int t = threadIdx.x;
    const int wid = t >> 5;
    const int lane = t & 31;
    const int g = blockIdx.x;
    const int fg = lane >> 2;
    const int tig = lane & 3;

    // ---- block 0: loads + zeros ----
    for (int i = t; i < 384; i += 256) pos1L[i] = pos1[g * 384 + i];
    for (int i = t; i < 96;  i += 256) pos2L[i] = pos2[g * 96 + i];
    if (t < 64) { W1lS[t] = W1l[t]; b2lS[t] = b2l[t]; }
    if (t < 16) b1lS[t] = b1l[t];
    for (int i = t; i < 512; i += 256) W1gS[i] = W1g[i];
    if (t < 32) b1gS[t] = b1g[t];
    for (int i = t; i < 128; i += 256) { b2gS[i] = b2g[i]; b3lS[i] = b3l[i]; cnt1i[i] = 0; }
    for (int i = t; i < 384; i += 256) W3P[i] = W3l[128 * 128 + i];
    if (t < 32) cnt2i[t] = 0;
    for (int i = t; i < 2112; i += 256) agg1T[i] = 0.f;
    __syncthreads();

    // ---- block 1: stage points + counts ----
    for (int p = t; p < 512; p += 256) {
        stX[p] = rgb[g * 512 + p];
        int s = (idx0[g * 512 + p] - g * CPG) & (CPG - 1);
        stS[p] = s;
        atomicAdd(&cnt1i[s], 1);
    }
    for (int i = t; i < 1536; i += 256) {
        float v = pos[g * 1536 + i];
        int p = i / 3, c = i - p * 3;
        if (c == 0) stPx[p] = v; else if (c == 1) stPy[p] = v; else stPz[p] = v;
    }
    if (t < 128) {
        int s = (idx1[g * 128 + t] - g * CPG2) & (CPG2 - 1);
        s1[t] = s;
        atomicAdd(&cnt2i[s], 1);
    }
    __syncthreads();

    // ---- block 2: prefix sums ----
    if (t < 32) {
        int carry = 0;
        for (int c = 0; c < 4; c++) {
            int v = cnt1i[c * 32 + t];
            int x = v;
            #pragma unroll
            for (int d = 1; d < 32; d <<= 1) {
                int y = __shfl_up_sync(0xffffffffu, x, d);
                if (t >= d) x += y;
            }
            int excl = x - v + carry;
            off1[c * 32 + t] = excl;
            off1f[c * 32 + t] = excl;
            carry += __shfl_sync(0xffffffffu, x, 31);
        }
    } else if (t < 64) {
        int ln = t - 32;
        int v = cnt2i[ln];
        int x = v;
        #pragma unroll
        for (int d = 1; d < 32; d <<= 1) {
            int y = __shfl_up_sync(0xffffffffu, x, d);
            if (ln >= d) x += y;
        }
        off2f[ln] = x - v;
    }
    __syncthreads();

    // ---- block 3: scatter sorted point list + row slots ----
    for (int p = t; p < 512; p += 256) {
        int s = stS[p];
        int pp = atomicAdd(&off1f[s], 1);
        plist[pp] = p;
    }
    if (t < 128) {
        int s = s1[t];
        int q = atomicAdd(&off2f[s], 1);
        slot[t] = q;
        sseg[q] = s;
    }
    __syncthreads();

    // ---- block 4: phase-1 accumulate + rel/pad rows into aP2 ----
    {
        int s = t >> 1, jb = (t & 1) * 8;
        int cnt = cnt1i[s], base = off1[s];
        float acc[8];
        #pragma unroll
        for (int j = 0; j < 8; j++) acc[j] = 0.f;
        const float c1x = pos1L[s * 3 + 0], c1y = pos1L[s * 3 + 1], c1z = pos1L[s * 3 + 2];
        for (int e = 0; e < cnt; e++) {
            int p = plist[base + e];
            float x0 = stX[p];
            float rx = stPx[p] - c1x, ry = stPy[p] - c1y, rz = stPz[p] - c1z;
            #pragma unroll
            for (int j = 0; j < 8; j++) {
                float h = b1lS[jb + j] + x0 * W1lS[jb + j] + rx * W1lS[16 + jb + j]
                        + ry * W1lS[32 + jb + j] + rz * W1lS[48 + jb + j];
                acc[j] += celu1(h);
            }
        }
        float inv = 1.f / (float)max(cnt, 1);
        #pragma unroll
        for (int j = 0; j < 8; j++) agg1T[(jb + j) * 132 + s] = acc[j] * inv;
    }
    if (t < 128) {
        int r = t, q = slot[r], s = s1[r];
        __half* row = aP2 + q * KP2;
        row[32] = __float2half(pos1L[r * 3 + 0] - pos2L[s * 3 + 0]);
        row[33] = __float2half(pos1L[r * 3 + 1] - pos2L[s * 3 + 1]);
        row[34] = __float2half(pos1L[r * 3 + 2] - pos2L[s * 3 + 2]);
        #pragma unroll
        for (int k = 35; k < 48; k++) row[k] = __float2half(0.f);
    }
    __syncthreads();

    // ---- f1 GEMM (scalar, tiny) -> aP2 cols 0..31 ; also zero agg2T ----
    {
        int ob = t & 7, rb = t >> 3;
        int r0 = rb * 4, o0 = ob * 4;
        float acc[4][4];
        #pragma unroll
        for (int ri = 0; ri < 4; ri++)
            #pragma unroll
            for (int oi = 0; oi < 4; oi++) acc[ri][oi] = b1gS[o0 + oi];
        #pragma unroll
        for (int j = 0; j < 16; j++) {
            float4 x = *(const float4*)&agg1T[j * 132 + r0];
            float4 w = *(const float4*)&W1gS[j * 32 + o0];
            float xa[4] = {x.x, x.y, x.z, x.w};
            float wa[4] = {w.x, w.y, w.z, w.w};
            #pragma unroll
            for (int ri = 0; ri < 4; ri++)
                #pragma unroll
                for (int oi = 0; oi < 4; oi++) acc[ri][oi] += xa[ri] * wa[oi];
        }
        #pragma unroll
        for (int ri = 0; ri < 4; ri++) {
            int q = slot[r0 + ri];
            *(__half2*)&aP2[q * KP2 + o0]     = __floats2half2_rn(celu1(acc[ri][0]), celu1(acc[ri][1]));
            *(__half2*)&aP2[q * KP2 + o0 + 2] = __floats2half2_rn(celu1(acc[ri][2]), celu1(acc[ri][3]));
        }
    }
    for (int i = t; i < 64 * 36; i += 256) agg2T[i] = 0.f;
    __syncthreads();

    // ---- P2 HMMA: C[128x64] = aP2[128x48] @ W2l^T (B frags from L2) ----
    {
        float c[8][4];
        #pragma unroll
        for (int nt = 0; nt < 8; nt++)
            #pragma unroll
            for (int i = 0; i < 4; i++) c[nt][i] = 0.f;
        const __half* A = aP2 + wid * 16 * KP2;
        #pragma unroll
        for (int ks = 0; ks < 3; ks++) {
            uint32_t a[4];
            ldA(a, A, KP2, fg, tig, ks * 16);
            #pragma unroll
            for (int nt = 0; nt < 8; nt++) {
                const __half* B = g_w2lH + (nt * 8 + fg) * KP2 + ks * 16 + tig * 2;
                uint32_t b0 = __ldg((const uint32_t*)B);
                uint32_t b1 = __ldg((const uint32_t*)(B + 8));
                mma16816(c[nt], a, b0, b1);
            }
        }
        int row0 = wid * 16 + fg;
        int s0 = sseg[row0], s2 = sseg[row0 + 8];
        #pragma unroll
        for (int nt = 0; nt < 8; nt++) {
            int o = nt * 8 + tig * 2;
            atomicAdd(&agg2T[o * 36 + s0],       celu1(c[nt][0] + b2lS[o]));
            atomicAdd(&agg2T[(o + 1) * 36 + s0], celu1(c[nt][1] + b2lS[o + 1]));
            atomicAdd(&agg2T[o * 36 + s2],       celu1(c[nt][2] + b2lS[o]));
            atomicAdd(&agg2T[(o + 1) * 36 + s2], celu1(c[nt][3] + b2lS[o + 1]));
        }
    }
    __syncthreads();

    // ---- normalize + pack aF2[32][64] fp16 ----
    for (int i = t; i < 2048; i += 256) {
        int s = i >> 6, j = i & 63;
        float inv = 1.f / fmaxf((float)cnt2i[s], 1.f);
        aF2[s * KF2 + j] = __float2half(agg2T[j * 36 + s] * inv);
    }
    __syncthreads();

    // ---- F2 HMMA: C[32x128] = aF2[32x64] @ W2g^T ----
    {
        int rt = wid >> 2, nr = wid & 3;
        float c[4][4];
        #pragma unroll
        for (int nt = 0; nt < 4; nt++)
            #pragma unroll
            for (int i = 0; i < 4; i++) c[nt][i] = 0.f;
        const __half* A = aF2 + rt * 16 * KF2;
        #pragma unroll
        for (int ks = 0; ks < 4; ks++) {
            uint32_t a[4];
            ldA(a, A, KF2, fg, tig, ks * 16);
            #pragma unroll
            for (int nt = 0; nt < 4; nt++) {
                const __half* B = g_w2gH + (nr * 32 + nt * 8 + fg) * KF2 + ks * 16 + tig * 2;
                uint32_t b0 = __ldg((const uint32_t*)B);
                uint32_t b1 = __ldg((const uint32_t*)(B + 8));
                mma16816(c[nt], a, b0, b1);
            }
        }
        int srow0 = rt * 16 + fg;
        #pragma unroll
        for (int nt = 0; nt < 4; nt++) {
            int o = nr * 32 + nt * 8 + tig * 2;
            *(__half2*)&aP3[srow0 * KP3 + o] =
                __floats2half2_rn(celu1(c[nt][0] + b2gS[o]), celu1(c[nt][1] + b2gS[o + 1]));
            *(__half2*)&aP3[(srow0 + 8) * KP3 + o] =
                __floats2half2_rn(celu1(c[nt][2] + b2gS[o]), celu1(c[nt][3] + b2gS[o + 1]));
        }
    }
    __syncthreads();

    // ---- P3 HMMA: C[32x128] = aP3[32x128] @ W3l^T(rows 0..127) ----
    {
        int rt = wid >> 2, nr = wid & 3;
        float c[4][4];
        #pragma unroll
        for (int nt = 0; nt < 4; nt++)
            #pragma unroll
            for (int i = 0; i < 4; i++) c[nt][i] = 0.f;
        const __half* A = aP3 + rt * 16 * KP3;
        #pragma unroll
        for (int ks = 0; ks < 8; ks++) {
            uint32_t a[4];
            ldA(a, A, KP3, fg, tig, ks * 16);
            #pragma unroll
            for (int nt = 0; nt < 4; nt++) {
                const __half* B = g_w3lH + (nr * 32 + nt * 8 + fg) * KP3 + ks * 16 + tig * 2;
                uint32_t b0 = __ldg((const uint32_t*)B);
                uint32_t b1 = __ldg((const uint32_t*)(B + 8));
                mma16816(c[nt], a, b0, b1);
            }
        }
        __syncthreads();   // agg2T region fully consumed; safe to overwrite as P3tmp
        int s0 = rt * 16 + fg, s2 = s0 + 8;
        float px0 = pos2L[s0 * 3], py0 = pos2L[s0 * 3 + 1], pz0 = pos2L[s0 * 3 + 2];
        float px2 = pos2L[s2 * 3], py2 = pos2L[s2 * 3 + 1], pz2 = pos2L[s2 * 3 + 2];
        #pragma unroll
        for (int nt = 0; nt < 4; nt++) {
            int o = nr * 32 + nt * 8 + tig * 2;
            #pragma unroll
            for (int oi = 0; oi < 2; oi++) {
                int oo = o + oi;
                float pp0 = px0 * W3P[oo] + py0 * W3P[128 + oo] + pz0 * W3P[256 + oo];
                float pp2 = px2 * W3P[oo] + py2 * W3P[128 + oo] + pz2 * W3P[256 + oo];
                P3tmp[s0 * 133 + oo] = celu1(c[nt][oi] + pp0 + b3lS[oo]);
                P3tmp[s2 * 133 + oo] = celu1(c[nt][2 + oi] + pp2 + b3lS[oo]);
            }
        }
    }
    __syncthreads();

    // write fp16 A-image row for tail GEMM1 (cols 128..135 zero-padded)
    if (t < 128) {
        float sum = 0.f;
        #pragma unroll 8
        for (int s = 0; s < 32; s++) sum += P3tmp[s * 133 + t];
        g_a3H[g * KP3 + t] = __float2half(sum * (1.f / 32.f));
    } else if (t < 136) {
        g_a3H[g * KP3 + t] = __float2half(0.f);
    }
}

// ---------------------------------------------------------------------------
// Tail: HMMA. 16 glimpses per CTA (grid 128), 512 threads = 16 warps.
//   GEMM1: f3[16x256] = celu(a3H[16x128] @ W3g^T + b3g)   (A,B frags via L2)
//   GEMM2: o[16x256]  = f3 @ Wlin^T + blin                (A from smem fp16)
// Warp w: rows fg, fg+8 (of 16); cols w*16 + nt*8 + tig*2, nt in {0,1}.
// ---------------------------------------------------------------------------
#define TGPB 16
__global__ __launch_bounds__(512) void tail_kernel(
    const float* __restrict__ b3g, const float* __restrict__ blin,
    const float* __restrict__ eps, float* __restrict__ out)
{
    __shared__ __align__(16) __half f3h[TGPB * KLN];   // 8448B
    __shared__ __align__(16) float  sO[TGPB * KLN];    // 16896B

    const int t = threadIdx.x;
    const int wid = t >> 5;
    const int lane = t & 31;
    const int fg = lane >> 2;
    const int tig = lane & 3;
    const int g0 = blockIdx.x * TGPB;

    // ---- GEMM1: K=128, A rows = glimpses (fp16 image in L2) ----
    {
        float c[2][4];
        #pragma unroll
        for (int nt = 0; nt < 2; nt++)
            #pragma unroll
            for (int i = 0; i < 4; i++) c[nt][i] = 0.f;
        const __half* A = g_a3H + (size_t)g0 * KP3;
        #pragma unroll
        for (int ks = 0; ks < 8; ks++) {
            uint32_t a[4];
            a[0] = __ldg((const uint32_t*)(A + fg * KP3 + ks * 16 + tig * 2));
            a[1] = __ldg((const uint32_t*)(A + (fg + 8) * KP3 + ks * 16 + tig * 2));
            a[2] = __ldg((const uint32_t*)(A + fg * KP3 + ks * 16 + 8 + tig * 2));
            a[3] = __ldg((const uint32_t*)(A + (fg + 8) * KP3 + ks * 16 + 8 + tig * 2));
            #pragma unroll
            for (int nt = 0; nt < 2; nt++) {
                const __half* B = g_w3gT + (wid * 16 + nt * 8 + fg) * KP3 + ks * 16 + tig * 2;
                uint32_t b0 = __ldg((const uint32_t*)B);
                uint32_t b1 = __ldg((const uint32_t*)(B + 8));
                mma16816(c[nt], a, b0, b1);
            }
        }
        // epilogue: celu + b3g -> f output (fp32) + f3h (fp16)
        #pragma unroll
        for (int nt = 0; nt < 2; nt++) {
            int o = wid * 16 + nt * 8 + tig * 2;
            float v00 = celu1(c[nt][0] + __ldg(&b3g[o]));
            float v01 = celu1(c[nt][1] + __ldg(&b3g[o + 1]));
            float v10 = celu1(c[nt][2] + __ldg(&b3g[o]));
            float v11 = celu1(c[nt][3] + __ldg(&b3g[o + 1]));
            out[786432 + (size_t)(g0 + fg) * 256 + o]     = v00;
            out[786432 + (size_t)(g0 + fg) * 256 + o + 1] = v01;
            out[786432 + (size_t)(g0 + fg + 8) * 256 + o]     = v10;
            out[786432 + (size_t)(g0 + fg + 8) * 256 + o + 1] = v11;
            *(__half2*)&f3h[fg * KLN + o]       = __floats2half2_rn(v00, v01);
            *(__half2*)&f3h[(fg + 8) * KLN + o] = __floats2half2_rn(v10, v11);
        }
    }
    __syncthreads();

    // ---- GEMM2: K=256, A = f3h (smem) ----
    {
        float c[2][4];
        #pragma unroll
        for (int nt = 0; nt < 2; nt++)
            #pragma unroll
            for (int i = 0; i < 4; i++) c[nt][i] = 0.f;
        #pragma unroll
        for (int ks = 0; ks < 16; ks++) {
            uint32_t a[4];
            ldA(a, f3h, KLN, fg, tig, ks * 16);
            #pragma unroll
            for (int nt = 0; nt < 2; nt++) {
                const __half* B = g_wlinT + (wid * 16 + nt * 8 + fg) * KLN + ks * 16 + tig * 2;
                uint32_t b0 = __ldg((const uint32_t*)B);
                uint32_t b1 = __ldg((const uint32_t*)(B + 8));
                mma16816(c[nt], a, b0, b1);
            }
        }
        #pragma unroll
        for (int nt = 0; nt < 2; nt++) {
            int o = wid * 16 + nt * 8 + tig * 2;
            sO[fg * KLN + o]           = c[nt][0] + __ldg(&blin[o]);
            sO[fg * KLN + o + 1]       = c[nt][1] + __ldg(&blin[o + 1]);
            sO[(fg + 8) * KLN + o]     = c[nt][2] + __ldg(&blin[o]);
            sO[(fg + 8) * KLN + o + 1] = c[nt][3] + __ldg(&blin[o + 1]);
        }
    }
    __syncthreads();

    // ---- final: split, softplus, sample ----
    for (int i = t; i < TGPB * 128; i += 512) {
        int gg = i >> 7, c = i & 127;
        int gid = g0 + gg;
        float mu = sO[gg * KLN + c];
        float sg = sO[gg * KLN + 128 + c];
        float sigma = (sg > 20.f) ? sg : log1pf(expf(sg));
        float z = mu + sigma * eps[gid * 128 + c];
        if (c < 64) out[(size_t)gid * 64 + c] = z;
        else        out[131072 + (size_t)gid * 64 + (c - 64)] = z;
        out[262144 + (size_t)gid * 128 + c] = mu;
        out[524288 + (size_t)gid * 128 + c] = sigma;
    }
}

extern "C" void kernel_launch(void* const* d_in, const int* in_sizes, int n_in,
                              void* d_out, int out_size)
{
    (void)in_sizes; (void)n_in; (void)out_size;
    const float* rgb  = (const float*)d_in[0];
    const float* pos  = (const float*)d_in[1];
    const float* pos1 = (const float*)d_in[2];
    const float* pos2 = (const float*)d_in[3];
    const int*   idx0 = (const int*)d_in[4];
    const int*   idx1 = (const int*)d_in[5];
    // d_in[6] (out_index2) unused: structure implied
    const float* eps  = (const float*)d_in[7];
    const float* W1l  = (const float*)d_in[8];
    const float* b1l  = (const float*)d_in[9];
    const float* W1g  = (const float*)d_in[10];
    const float* b1g  = (const float*)d_in[11];
    const float* W2l  = (const float*)d_in[12];
    const float* b2l  = (const float*)d_in[13];
    const float* W2g  = (const float*)d_in[14];
    const float* b2g  = (const float*)d_in[15];
    const float* W3l  = (const float*)d_in[16];
    const float* b3l  = (const float*)d_in[17];
    const float* W3g  = (const float*)d_in[18];
    const float* b3g  = (const float*)d_in[19];
    const float* Wlin = (const float*)d_in[20];
    const float* blin = (const float*)d_in[21];
    float* out = (float*)d_out;

    cudaFuncSetAttribute(glimpse_kernel, cudaFuncAttributeMaxDynamicSharedMemorySize, SMEM_BYTES);

    prep_kernel<<<(PREP_ELEMS + 255) / 256, 256>>>(W2l, W2g, W3l, W3g, Wlin);
    glimpse_kernel<<<NG, 256, SMEM_BYTES>>>(rgb, pos, pos1, pos2, idx0, idx1,
                                            W1l, b1l, W1g, b1g, b2l, b2g, W3l, b3l);
    tail_kernel<<<NG / TGPB, 512>>>(b3g, blin, eps, out);
}